// round 1
// baseline (speedup 1.0000x reference)
#include <cuda_runtime.h>
#include <cuda_bf16.h>
#include <math.h>

// ---------------- problem constants ----------------
#define BB 2
#define LL 2048
#define NC 3
#define DMC 256
#define DM 768          // DMC*NC
#define DI 1536         // 2*DM
#define DS 16
#define DR 48
#define DCV 4
#define NLAY 4
#define DXP 80          // DR + 2*DS
#define NROWS (BB*LL)   // 4096

// ---------------- scratch (device globals; no allocs) ----------------
__device__ float g_H[NROWS*DM];        // residual stream
__device__ float g_XN[NROWS*DM];       // rmsnorm output
__device__ float g_XZ[NROWS*2*DI];     // in_proj output (xin | z)
__device__ float g_U[NROWS*DI];        // conv + silu output
__device__ float g_DBC[NROWS*DXP];     // x_proj output
__device__ float g_DELTA[NROWS*DI];    // softplus(dt_proj)
__device__ float g_Y[NROWS*DI];        // gated scan output

// ---------------- embedding gather ----------------
__global__ void embed_kernel(const int* __restrict__ tokens,
                             const float* __restrict__ emb) {
    int i = blockIdx.x * blockDim.x + threadIdx.x;
    if (i >= NROWS*DM) return;
    int row = i / DM;
    int col = i % DM;
    int c = col / DMC, j = col % DMC;
    int tok = tokens[row*NC + c];
    g_H[i] = emb[tok*DMC + j];
}

// ---------------- rmsnorm (one block per row) ----------------
__global__ void rmsnorm_kernel(const float* __restrict__ in,
                               const float* __restrict__ w,
                               float* __restrict__ out) {
    int row = blockIdx.x;
    const float* x = in + (size_t)row*DM;
    float s = 0.f;
    for (int i = threadIdx.x; i < DM; i += 256) { float v = x[i]; s += v*v; }
    __shared__ float red[256];
    red[threadIdx.x] = s;
    __syncthreads();
    for (int o = 128; o; o >>= 1) {
        if (threadIdx.x < o) red[threadIdx.x] += red[threadIdx.x + o];
        __syncthreads();
    }
    float scale = rsqrtf(red[0] / (float)DM + 1e-5f);
    for (int i = threadIdx.x; i < DM; i += 256)
        out[(size_t)row*DM + i] = x[i] * scale * w[i];
}

// ---------------- generic tiled GEMM:  C[M,N] = A[M,K(lda)] * W[N,K]^T ----------------
// EPI: 0 = store, 1 = C += acc (residual), 2 = softplus(acc + bias[n])
#define BM 64
#define BN 64
#define BK 16

template<int EPI>
__global__ void gemm_tn(const float* __restrict__ A, const float* __restrict__ W,
                        float* __restrict__ C, const float* __restrict__ bias,
                        int M, int N, int K, int lda) {
    __shared__ float As[BK][BM + 1];
    __shared__ float Ws[BK][BN + 1];
    int n0 = blockIdx.x * BN;
    int m0 = blockIdx.y * BM;
    int tid = threadIdx.x;            // 256 threads
    int tx = tid & 15, ty = tid >> 4; // 16x16 thread grid, 4x4 per thread
    float acc[4][4] = {};

    for (int k0 = 0; k0 < K; k0 += BK) {
        #pragma unroll
        for (int it = 0; it < 4; it++) {
            int idx = it*256 + tid;
            int r = idx >> 4, kk = idx & 15;
            As[kk][r] = A[(size_t)(m0 + r)*lda + k0 + kk];   // M always multiple of 64
        }
        #pragma unroll
        for (int it = 0; it < 4; it++) {
            int idx = it*256 + tid;
            int r = idx >> 4, kk = idx & 15;
            int n = n0 + r;
            Ws[kk][r] = (n < N) ? W[(size_t)n*K + k0 + kk] : 0.f;
        }
        __syncthreads();
        #pragma unroll
        for (int kk = 0; kk < BK; kk++) {
            float a[4], b[4];
            #pragma unroll
            for (int i = 0; i < 4; i++) a[i] = As[kk][ty*4 + i];
            #pragma unroll
            for (int j = 0; j < 4; j++) b[j] = Ws[kk][tx*4 + j];
            #pragma unroll
            for (int i = 0; i < 4; i++)
                #pragma unroll
                for (int j = 0; j < 4; j++)
                    acc[i][j] += a[i] * b[j];
        }
        __syncthreads();
    }

    #pragma unroll
    for (int i = 0; i < 4; i++) {
        int m = m0 + ty*4 + i;
        #pragma unroll
        for (int j = 0; j < 4; j++) {
            int n = n0 + tx*4 + j;
            if (n >= N) continue;
            size_t idx = (size_t)m*N + n;
            if (EPI == 0) {
                C[idx] = acc[i][j];
            } else if (EPI == 1) {
                C[idx] += acc[i][j];
            } else {
                float v = acc[i][j] + bias[n];
                // softplus
                C[idx] = (v > 20.f) ? v : log1pf(expf(v));
            }
        }
    }
}

// ---------------- depthwise causal conv (DC=4) + bias + silu ----------------
__global__ void conv_silu_kernel(const float* __restrict__ cw,
                                 const float* __restrict__ cb) {
    int i = blockIdx.x * blockDim.x + threadIdx.x;
    if (i >= NROWS*DI) return;
    int d = i % DI;
    int row = i / DI;
    int t = row % LL, b = row / LL;
    float w0 = cw[d*DCV + 0], w1 = cw[d*DCV + 1], w2 = cw[d*DCV + 2], w3 = cw[d*DCV + 3];
    float acc = cb[d];
    const float* base = g_XZ + (size_t)(b*LL)* (2*DI) + d;
    if (t >= 3) acc += base[(size_t)(t-3)*(2*DI)] * w0;
    if (t >= 2) acc += base[(size_t)(t-2)*(2*DI)] * w1;
    if (t >= 1) acc += base[(size_t)(t-1)*(2*DI)] * w2;
    acc += base[(size_t)t*(2*DI)] * w3;
    g_U[i] = acc / (1.f + expf(-acc));   // silu
}

// ---------------- selective scan + skip + gating ----------------
// One channel (b,d) per 16-lane group; lane s owns state h[s].
__global__ void scan_kernel(const float* __restrict__ A_log_l,
                            const float* __restrict__ D_l) {
    int g = threadIdx.x >> 4;
    int s = threadIdx.x & 15;
    int ch = blockIdx.x * 16 + g;          // 0 .. B*DI-1
    int b = ch / DI, d = ch % DI;

    float A = -expf(A_log_l[d*DS + s]);
    float Dd = D_l[d];
    float h = 0.f;

    const float* delta_p = g_DELTA + (size_t)(b*LL)*DI + d;
    const float* u_p     = g_U     + (size_t)(b*LL)*DI + d;
    const float* z_p     = g_XZ    + (size_t)(b*LL)*(2*DI) + DI + d;
    const float* dbc_p   = g_DBC   + (size_t)(b*LL)*DXP;
    float* y_p           = g_Y     + (size_t)(b*LL)*DI + d;

    for (int t = 0; t < LL; t++) {
        float dt = delta_p[(size_t)t*DI];
        float ut = u_p[(size_t)t*DI];
        float Bs = dbc_p[(size_t)t*DXP + DR + s];
        float Cs = dbc_p[(size_t)t*DXP + DR + DS + s];
        float dA = __expf(dt * A);
        h = dA * h + (dt * ut) * Bs;
        float yv = h * Cs;
        // reduce over 16 lanes
        yv += __shfl_down_sync(0xffffffffu, yv, 8, 16);
        yv += __shfl_down_sync(0xffffffffu, yv, 4, 16);
        yv += __shfl_down_sync(0xffffffffu, yv, 2, 16);
        yv += __shfl_down_sync(0xffffffffu, yv, 1, 16);
        if (s == 0) {
            float z = z_p[(size_t)t*(2*DI)];
            float silu_z = z / (1.f + __expf(-z));
            y_p[(size_t)t*DI] = (yv + ut * Dd) * silu_z;
        }
    }
}

// ---------------- heads ----------------
__global__ void topic_kernel(const float* __restrict__ xfin,
                             const float* __restrict__ tw,
                             const float* __restrict__ tb,
                             float* __restrict__ out) {
    int w = threadIdx.x >> 5, lane = threadIdx.x & 31;
    if (w >= BB*3) return;
    int b = w / 3, c = w % 3;
    const float* p  = xfin + (size_t)(b*LL)*DM;   // pooled = x[b, 0, :]
    const float* wt = tw + (size_t)c*DM;
    float s = 0.f;
    for (int i = lane; i < DM; i += 32) s += p[i] * wt[i];
    for (int o = 16; o; o >>= 1) s += __shfl_down_sync(0xffffffffu, s, o);
    if (lane == 0) out[b*3 + c] = s + tb[c];
}

__global__ void loss_kernel(float* __restrict__ out, const int* __restrict__ labels) {
    if (threadIdx.x != 0 || blockIdx.x != 0) return;
    float sum = 0.f, cnt = 0.f;
    for (int b = 0; b < BB; b++) {
        float t0 = out[b*3+0], t1 = out[b*3+1], t2 = out[b*3+2];
        float m = fmaxf(t0, fmaxf(t1, t2));
        float lse = m + logf(expf(t0-m) + expf(t1-m) + expf(t2-m));
        int lab = labels[b];
        float nll = lse - out[b*3 + lab];
        if (lab != 0) { sum += nll; cnt += 1.f; }
    }
    out[6] = sum / fmaxf(cnt, 1.f);
}

// ---------------- driver ----------------
extern "C" void kernel_launch(void* const* d_in, const int* in_sizes, int n_in,
                              void* d_out, int out_size) {
    const int*   tokens    = (const int*)  d_in[0];
    const int*   labels    = (const int*)  d_in[1];
    const float* emb       = (const float*)d_in[2];
    const float* in_proj_w = (const float*)d_in[3];
    const float* conv_w    = (const float*)d_in[4];
    const float* conv_b    = (const float*)d_in[5];
    const float* x_proj_w  = (const float*)d_in[6];
    const float* dt_proj_w = (const float*)d_in[7];
    const float* dt_proj_b = (const float*)d_in[8];
    const float* A_log     = (const float*)d_in[9];
    const float* Dp        = (const float*)d_in[10];
    const float* out_proj_w= (const float*)d_in[11];
    const float* norm_w    = (const float*)d_in[12];
    const float* norm_f_w  = (const float*)d_in[13];
    const float* topic_w   = (const float*)d_in[14];
    const float* topic_b   = (const float*)d_in[15];
    float* out = (float*)d_out;

    float *pH, *pXN, *pXZ, *pU, *pDBC, *pDELTA, *pY;
    cudaGetSymbolAddress((void**)&pH,     g_H);
    cudaGetSymbolAddress((void**)&pXN,    g_XN);
    cudaGetSymbolAddress((void**)&pXZ,    g_XZ);
    cudaGetSymbolAddress((void**)&pU,     g_U);
    cudaGetSymbolAddress((void**)&pDBC,   g_DBC);
    cudaGetSymbolAddress((void**)&pDELTA, g_DELTA);
    cudaGetSymbolAddress((void**)&pY,     g_Y);

    // 1. embedding -> g_H
    embed_kernel<<<(NROWS*DM + 255)/256, 256>>>(tokens, emb);

    for (int l = 0; l < NLAY; l++) {
        const float* ipw = in_proj_w + (size_t)l * 2*DI * DM;
        const float* cw  = conv_w    + (size_t)l * DI * DCV;
        const float* cb  = conv_b    + (size_t)l * DI;
        const float* xpw = x_proj_w  + (size_t)l * DXP * DI;
        const float* dpw = dt_proj_w + (size_t)l * DI * DR;
        const float* dpb = dt_proj_b + (size_t)l * DI;
        const float* Al  = A_log     + (size_t)l * DI * DS;
        const float* Dl  = Dp        + (size_t)l * DI;
        const float* opw = out_proj_w+ (size_t)l * DM * DI;
        const float* nw  = norm_w    + (size_t)l * DM;

        // rmsnorm(h) -> XN
        rmsnorm_kernel<<<NROWS, 256>>>(pH, nw, pXN);

        // XZ = XN @ in_proj^T   (4096 x 3072, K=768)
        {
            dim3 grid(2*DI/BN, NROWS/BM);
            gemm_tn<0><<<grid, 256>>>(pXN, ipw, pXZ, nullptr, NROWS, 2*DI, DM, DM);
        }

        // conv + silu -> U
        conv_silu_kernel<<<(NROWS*DI + 255)/256, 256>>>(cw, cb);

        // DBC = U @ x_proj^T   (4096 x 80, K=1536)
        {
            dim3 grid((DXP + BN - 1)/BN, NROWS/BM);
            gemm_tn<0><<<grid, 256>>>(pU, xpw, pDBC, nullptr, NROWS, DXP, DI, DI);
        }

        // DELTA = softplus(DBC[:, :48] @ dt_proj^T + b)  (4096 x 1536, K=48)
        {
            dim3 grid(DI/BN, NROWS/BM);
            gemm_tn<2><<<grid, 256>>>(pDBC, dpw, pDELTA, dpb, NROWS, DI, DR, DXP);
        }

        // selective scan + gate -> Y
        scan_kernel<<<BB*DI/16, 256>>>(Al, Dl);

        // H += Y @ out_proj^T   (4096 x 768, K=1536)
        {
            dim3 grid(DM/BN, NROWS/BM);
            gemm_tn<1><<<grid, 256>>>(pY, opw, pH, nullptr, NROWS, DM, DI, DI);
        }
    }

    // final rmsnorm -> out[7:]
    rmsnorm_kernel<<<NROWS, 256>>>(pH, norm_f_w, out + 7);

    // topic logits -> out[0:6]
    topic_kernel<<<1, 192>>>(out + 7, topic_w, topic_b, out);

    // topic loss -> out[6]
    loss_kernel<<<1, 1>>>(out, labels);
}

// round 2
// speedup vs baseline: 1.1927x; 1.1927x over previous
#include <cuda_runtime.h>
#include <cuda_bf16.h>
#include <math.h>

// ---------------- problem constants ----------------
#define BB 2
#define LL 2048
#define NC 3
#define DMC 256
#define DM 768          // DMC*NC
#define DI 1536         // 2*DM
#define DS 16
#define DR 48
#define DCV 4
#define NLAY 4
#define DXP 80          // DR + 2*DS
#define NROWS (BB*LL)   // 4096

// ---------------- scratch (device globals; no allocs) ----------------
__device__ float g_H[NROWS*DM];        // residual stream
__device__ float g_XN[NROWS*DM];       // rmsnorm output
__device__ float g_XZ[NROWS*2*DI];     // in_proj output (xin | z)
__device__ float g_U[NROWS*DI];        // conv + silu output
__device__ float g_DBC[NROWS*DXP];     // x_proj output
__device__ float g_DELTA[NROWS*DI];    // softplus(dt_proj)
__device__ float g_Y[NROWS*DI];        // gated scan output

// ---------------- embedding gather ----------------
__global__ void embed_kernel(const int* __restrict__ tokens,
                             const float* __restrict__ emb) {
    int i = blockIdx.x * blockDim.x + threadIdx.x;
    if (i >= NROWS*DM) return;
    int row = i / DM;
    int col = i % DM;
    int c = col / DMC, j = col % DMC;
    int tok = tokens[row*NC + c];
    g_H[i] = emb[tok*DMC + j];
}

// ---------------- rmsnorm (one block per row) ----------------
__global__ void rmsnorm_kernel(const float* __restrict__ in,
                               const float* __restrict__ w,
                               float* __restrict__ out) {
    int row = blockIdx.x;
    const float* x = in + (size_t)row*DM;
    float s = 0.f;
    for (int i = threadIdx.x; i < DM; i += 256) { float v = x[i]; s += v*v; }
    __shared__ float red[256];
    red[threadIdx.x] = s;
    __syncthreads();
    for (int o = 128; o; o >>= 1) {
        if (threadIdx.x < o) red[threadIdx.x] += red[threadIdx.x + o];
        __syncthreads();
    }
    float scale = rsqrtf(red[0] / (float)DM + 1e-5f);
    for (int i = threadIdx.x; i < DM; i += 256)
        out[(size_t)row*DM + i] = x[i] * scale * w[i];
}

// ---------------- zero fill ----------------
__global__ void zero_kernel(float* __restrict__ p, int n) {
    int i = blockIdx.x * blockDim.x + threadIdx.x;
    if (i < n) p[i] = 0.f;
}

// ============================================================
// 128x128x16 SGEMM:  C[M,N] = A[M,lda-major] * W[N,ldw-major]^T
// 256 threads, 8x8 accum/thread (2x2 quadrants of 4x4),
// double-buffered smem, register prefetch, float4 loads.
// EPI: 0 = store, 1 = C += acc, 2 = softplus(acc+bias[n]), 3 = atomicAdd
// ============================================================
#define GBM 128
#define GBN 128
#define GBK 16

template<int EPI>
__global__ __launch_bounds__(256)
void gemm128(const float* __restrict__ A, const float* __restrict__ W,
             float* __restrict__ C, const float* __restrict__ bias,
             int N, int lda, int ldw, int kbeg, int kend) {
    __shared__ float As[2][GBK][GBM + 4];
    __shared__ float Ws[2][GBK][GBN + 4];

    int n0 = blockIdx.x * GBN;
    int m0 = blockIdx.y * GBM;
    int kz = blockIdx.z;
    int kchunk = kend - kbeg;      // per-z chunk handled by caller via kbeg/kend args
    int kb = kbeg + kz * kchunk;   // when gridDim.z>1, caller passes chunk size via kbeg=0,kend=chunk
    int ke = kb + kchunk;

    int tid = threadIdx.x;
    int lr = tid >> 1;             // 0..127 : row within tile
    int lk = (tid & 1) * 8;        // 0 or 8 : k offset

    int tx = tid & 15, ty = tid >> 4;

    const float* ap = A + (size_t)(m0 + lr)*lda + lk;
    bool wok = (n0 + lr) < N;
    const float* wp = W + (size_t)(wok ? (n0 + lr) : 0)*ldw + lk;

    float acc[2][2][4][4];
    #pragma unroll
    for (int a = 0; a < 2; a++)
        #pragma unroll
        for (int b = 0; b < 2; b++)
            #pragma unroll
            for (int i = 0; i < 4; i++)
                #pragma unroll
                for (int j = 0; j < 4; j++) acc[a][b][i][j] = 0.f;

    // prologue: load first tile
    float4 ra0 = *(const float4*)(ap + kb);
    float4 ra1 = *(const float4*)(ap + kb + 4);
    float4 rw0, rw1;
    if (wok) { rw0 = *(const float4*)(wp + kb); rw1 = *(const float4*)(wp + kb + 4); }
    else     { rw0 = make_float4(0,0,0,0); rw1 = rw0; }

    int buf = 0;
    {
        #pragma unroll
        for (int j = 0; j < 4; j++) {
            As[0][lk + j][lr]     = (&ra0.x)[j];
            As[0][lk + 4 + j][lr] = (&ra1.x)[j];
            Ws[0][lk + j][lr]     = (&rw0.x)[j];
            Ws[0][lk + 4 + j][lr] = (&rw1.x)[j];
        }
    }
    __syncthreads();

    for (int k0 = kb; k0 < ke; k0 += GBK) {
        bool has_next = (k0 + GBK) < ke;
        if (has_next) {
            ra0 = *(const float4*)(ap + k0 + GBK);
            ra1 = *(const float4*)(ap + k0 + GBK + 4);
            if (wok) { rw0 = *(const float4*)(wp + k0 + GBK); rw1 = *(const float4*)(wp + k0 + GBK + 4); }
        }
        #pragma unroll
        for (int kk = 0; kk < GBK; kk++) {
            float4 a0 = *(const float4*)&As[buf][kk][ty*4];
            float4 a1 = *(const float4*)&As[buf][kk][64 + ty*4];
            float4 b0 = *(const float4*)&Ws[buf][kk][tx*4];
            float4 b1 = *(const float4*)&Ws[buf][kk][64 + tx*4];
            const float* av[2] = { &a0.x, &a1.x };
            const float* bv[2] = { &b0.x, &b1.x };
            #pragma unroll
            for (int qa = 0; qa < 2; qa++)
                #pragma unroll
                for (int qb = 0; qb < 2; qb++)
                    #pragma unroll
                    for (int i = 0; i < 4; i++)
                        #pragma unroll
                        for (int j = 0; j < 4; j++)
                            acc[qa][qb][i][j] += av[qa][i] * bv[qb][j];
        }
        if (has_next) {
            int nb = buf ^ 1;
            #pragma unroll
            for (int j = 0; j < 4; j++) {
                As[nb][lk + j][lr]     = (&ra0.x)[j];
                As[nb][lk + 4 + j][lr] = (&ra1.x)[j];
                Ws[nb][lk + j][lr]     = (&rw0.x)[j];
                Ws[nb][lk + 4 + j][lr] = (&rw1.x)[j];
            }
            __syncthreads();
            buf = nb;
        }
    }

    #pragma unroll
    for (int qa = 0; qa < 2; qa++) {
        #pragma unroll
        for (int i = 0; i < 4; i++) {
            int m = m0 + qa*64 + ty*4 + i;
            #pragma unroll
            for (int qb = 0; qb < 2; qb++) {
                #pragma unroll
                for (int j = 0; j < 4; j++) {
                    int n = n0 + qb*64 + tx*4 + j;
                    if (n >= N) continue;
                    size_t idx = (size_t)m*N + n;
                    float v = acc[qa][qb][i][j];
                    if (EPI == 0)      C[idx] = v;
                    else if (EPI == 1) C[idx] += v;
                    else if (EPI == 2) {
                        float t = v + bias[n];
                        C[idx] = (t > 20.f) ? t : log1pf(expf(t));
                    } else {
                        atomicAdd(&C[idx], v);
                    }
                }
            }
        }
    }
}

// ---------------- depthwise causal conv (DC=4) + bias + silu ----------------
__global__ void conv_silu_kernel(const float* __restrict__ cw,
                                 const float* __restrict__ cb) {
    int i = blockIdx.x * blockDim.x + threadIdx.x;
    if (i >= NROWS*DI) return;
    int d = i % DI;
    int row = i / DI;
    int t = row % LL, b = row / LL;
    float w0 = cw[d*DCV + 0], w1 = cw[d*DCV + 1], w2 = cw[d*DCV + 2], w3 = cw[d*DCV + 3];
    float acc = cb[d];
    const float* base = g_XZ + (size_t)(b*LL)* (2*DI) + d;
    if (t >= 3) acc += base[(size_t)(t-3)*(2*DI)] * w0;
    if (t >= 2) acc += base[(size_t)(t-2)*(2*DI)] * w1;
    if (t >= 1) acc += base[(size_t)(t-1)*(2*DI)] * w2;
    acc += base[(size_t)t*(2*DI)] * w3;
    g_U[i] = acc / (1.f + expf(-acc));   // silu
}

// ---------------- selective scan + skip + gating ----------------
__global__ void scan_kernel(const float* __restrict__ A_log_l,
                            const float* __restrict__ D_l) {
    int g = threadIdx.x >> 4;
    int s = threadIdx.x & 15;
    int ch = blockIdx.x * 16 + g;          // 0 .. B*DI-1
    int b = ch / DI, d = ch % DI;

    float A = -expf(A_log_l[d*DS + s]);
    float Dd = D_l[d];
    float h = 0.f;

    const float* delta_p = g_DELTA + (size_t)(b*LL)*DI + d;
    const float* u_p     = g_U     + (size_t)(b*LL)*DI + d;
    const float* z_p     = g_XZ    + (size_t)(b*LL)*(2*DI) + DI + d;
    const float* dbc_p   = g_DBC   + (size_t)(b*LL)*DXP;
    float* y_p           = g_Y     + (size_t)(b*LL)*DI + d;

    for (int t = 0; t < LL; t++) {
        float dt = delta_p[(size_t)t*DI];
        float ut = u_p[(size_t)t*DI];
        float Bs = dbc_p[(size_t)t*DXP + DR + s];
        float Cs = dbc_p[(size_t)t*DXP + DR + DS + s];
        float dA = __expf(dt * A);
        h = dA * h + (dt * ut) * Bs;
        float yv = h * Cs;
        yv += __shfl_down_sync(0xffffffffu, yv, 8, 16);
        yv += __shfl_down_sync(0xffffffffu, yv, 4, 16);
        yv += __shfl_down_sync(0xffffffffu, yv, 2, 16);
        yv += __shfl_down_sync(0xffffffffu, yv, 1, 16);
        if (s == 0) {
            float z = z_p[(size_t)t*(2*DI)];
            float silu_z = z / (1.f + __expf(-z));
            y_p[(size_t)t*DI] = (yv + ut * Dd) * silu_z;
        }
    }
}

// ---------------- heads ----------------
__global__ void topic_kernel(const float* __restrict__ xfin,
                             const float* __restrict__ tw,
                             const float* __restrict__ tb,
                             float* __restrict__ out) {
    int w = threadIdx.x >> 5, lane = threadIdx.x & 31;
    if (w >= BB*3) return;
    int b = w / 3, c = w % 3;
    const float* p  = xfin + (size_t)(b*LL)*DM;
    const float* wt = tw + (size_t)c*DM;
    float s = 0.f;
    for (int i = lane; i < DM; i += 32) s += p[i] * wt[i];
    for (int o = 16; o; o >>= 1) s += __shfl_down_sync(0xffffffffu, s, o);
    if (lane == 0) out[b*3 + c] = s + tb[c];
}

__global__ void loss_kernel(float* __restrict__ out, const int* __restrict__ labels) {
    if (threadIdx.x != 0 || blockIdx.x != 0) return;
    float sum = 0.f, cnt = 0.f;
    for (int b = 0; b < BB; b++) {
        float t0 = out[b*3+0], t1 = out[b*3+1], t2 = out[b*3+2];
        float m = fmaxf(t0, fmaxf(t1, t2));
        float lse = m + logf(expf(t0-m) + expf(t1-m) + expf(t2-m));
        int lab = labels[b];
        float nll = lse - out[b*3 + lab];
        if (lab != 0) { sum += nll; cnt += 1.f; }
    }
    out[6] = sum / fmaxf(cnt, 1.f);
}

// ---------------- driver ----------------
extern "C" void kernel_launch(void* const* d_in, const int* in_sizes, int n_in,
                              void* d_out, int out_size) {
    const int*   tokens    = (const int*)  d_in[0];
    const int*   labels    = (const int*)  d_in[1];
    const float* emb       = (const float*)d_in[2];
    const float* in_proj_w = (const float*)d_in[3];
    const float* conv_w    = (const float*)d_in[4];
    const float* conv_b    = (const float*)d_in[5];
    const float* x_proj_w  = (const float*)d_in[6];
    const float* dt_proj_w = (const float*)d_in[7];
    const float* dt_proj_b = (const float*)d_in[8];
    const float* A_log     = (const float*)d_in[9];
    const float* Dp        = (const float*)d_in[10];
    const float* out_proj_w= (const float*)d_in[11];
    const float* norm_w    = (const float*)d_in[12];
    const float* norm_f_w  = (const float*)d_in[13];
    const float* topic_w   = (const float*)d_in[14];
    const float* topic_b   = (const float*)d_in[15];
    float* out = (float*)d_out;

    float *pH, *pXN, *pXZ, *pU, *pDBC, *pDELTA, *pY;
    cudaGetSymbolAddress((void**)&pH,     g_H);
    cudaGetSymbolAddress((void**)&pXN,    g_XN);
    cudaGetSymbolAddress((void**)&pXZ,    g_XZ);
    cudaGetSymbolAddress((void**)&pU,     g_U);
    cudaGetSymbolAddress((void**)&pDBC,   g_DBC);
    cudaGetSymbolAddress((void**)&pDELTA, g_DELTA);
    cudaGetSymbolAddress((void**)&pY,     g_Y);

    embed_kernel<<<(NROWS*DM + 255)/256, 256>>>(tokens, emb);

    for (int l = 0; l < NLAY; l++) {
        const float* ipw = in_proj_w + (size_t)l * 2*DI * DM;
        const float* cw  = conv_w    + (size_t)l * DI * DCV;
        const float* cb  = conv_b    + (size_t)l * DI;
        const float* xpw = x_proj_w  + (size_t)l * DXP * DI;
        const float* dpw = dt_proj_w + (size_t)l * DI * DR;
        const float* dpb = dt_proj_b + (size_t)l * DI;
        const float* Al  = A_log     + (size_t)l * DI * DS;
        const float* Dl  = Dp        + (size_t)l * DI;
        const float* opw = out_proj_w+ (size_t)l * DM * DI;
        const float* nw  = norm_w    + (size_t)l * DM;

        // rmsnorm(h) -> XN
        rmsnorm_kernel<<<NROWS, 256>>>(pH, nw, pXN);

        // XZ = XN @ in_proj^T   (4096 x 3072, K=768)
        {
            dim3 grid(2*DI/GBN, NROWS/GBM, 1);
            gemm128<0><<<grid, 256>>>(pXN, ipw, pXZ, nullptr, 2*DI, DM, DM, 0, DM);
        }

        // conv + silu -> U
        conv_silu_kernel<<<(NROWS*DI + 255)/256, 256>>>(cw, cb);

        // DBC = U @ x_proj^T   (4096 x 80, K=1536)  split-K=8, atomic accumulate
        zero_kernel<<<(NROWS*DXP + 255)/256, 256>>>(pDBC, NROWS*DXP);
        {
            dim3 grid(1, NROWS/GBM, 8);
            // each z-slice handles K chunk of 1536/8 = 192 (passed as kbeg=0,kend=192)
            gemm128<3><<<grid, 256>>>(pU, xpw, pDBC, nullptr, DXP, DI, DI, 0, DI/8);
        }

        // DELTA = softplus(DBC[:, :48] @ dt_proj^T + b)  (4096 x 1536, K=48)
        {
            dim3 grid(DI/GBN, NROWS/GBM, 1);
            gemm128<2><<<grid, 256>>>(pDBC, dpw, pDELTA, dpb, DI, DXP, DR, 0, DR);
        }

        // selective scan + gate -> Y
        scan_kernel<<<BB*DI/16, 256>>>(Al, Dl);

        // H += Y @ out_proj^T   (4096 x 768, K=1536)
        {
            dim3 grid(DM/GBN, NROWS/GBM, 1);
            gemm128<1><<<grid, 256>>>(pY, opw, pH, nullptr, DM, DI, DI, 0, DI);
        }
    }

    // final rmsnorm -> out[7:]
    rmsnorm_kernel<<<NROWS, 256>>>(pH, norm_f_w, out + 7);

    // topic logits -> out[0:6]
    topic_kernel<<<1, 192>>>(out + 7, topic_w, topic_b, out);

    // topic loss -> out[6]
    loss_kernel<<<1, 1>>>(out, labels);
}

// round 3
// speedup vs baseline: 1.2452x; 1.0440x over previous
#include <cuda_runtime.h>
#include <cuda_bf16.h>
#include <math.h>

// ---------------- problem constants ----------------
#define BB 2
#define LL 2048
#define NC 3
#define DMC 256
#define DM 768          // DMC*NC
#define DI 1536         // 2*DM
#define DS 16
#define DR 48
#define DCV 4
#define NLAY 4
#define DXP 80          // DR + 2*DS
#define NROWS (BB*LL)   // 4096

// ---------------- scratch (device globals; no allocs) ----------------
__device__ float g_H[NROWS*DM];
__device__ float g_XN[NROWS*DM];
__device__ float g_XZ[NROWS*2*DI];
__device__ float g_U[NROWS*DI];
__device__ float g_DBC[NROWS*DXP];
__device__ float g_DELTA[NROWS*DI];
__device__ float g_Y[NROWS*DI];

// ---------------- embedding gather ----------------
__global__ void embed_kernel(const int* __restrict__ tokens,
                             const float* __restrict__ emb) {
    int i = blockIdx.x * blockDim.x + threadIdx.x;
    if (i >= NROWS*DM) return;
    int row = i / DM;
    int col = i % DM;
    int c = col / DMC, j = col % DMC;
    int tok = tokens[row*NC + c];
    g_H[i] = emb[tok*DMC + j];
}

// ---------------- rmsnorm ----------------
__global__ void rmsnorm_kernel(const float* __restrict__ in,
                               const float* __restrict__ w,
                               float* __restrict__ out) {
    int row = blockIdx.x;
    const float* x = in + (size_t)row*DM;
    float s = 0.f;
    for (int i = threadIdx.x; i < DM; i += 256) { float v = x[i]; s += v*v; }
    __shared__ float red[256];
    red[threadIdx.x] = s;
    __syncthreads();
    for (int o = 128; o; o >>= 1) {
        if (threadIdx.x < o) red[threadIdx.x] += red[threadIdx.x + o];
        __syncthreads();
    }
    float scale = rsqrtf(red[0] / (float)DM + 1e-5f);
    for (int i = threadIdx.x; i < DM; i += 256)
        out[(size_t)row*DM + i] = x[i] * scale * w[i];
}

// ---------------- zero fill ----------------
__global__ void zero_kernel(float* __restrict__ p, int n) {
    int i = blockIdx.x * blockDim.x + threadIdx.x;
    if (i < n) p[i] = 0.f;
}

// ============================================================
// 128x128x16 SGEMM:  C[M,N] = A[M,lda] * W[N,ldw]^T
// 256 threads, 8x8 accum/thread. No pointer arrays: explicit
// component moves into flat register arrays, fully unrolled.
// EPI: 0 = store, 1 = C += acc, 2 = softplus(acc+bias[n]), 3 = atomicAdd
// ============================================================
#define GBM 128
#define GBN 128
#define GBK 16

template<int EPI>
__global__ __launch_bounds__(256, 2)
void gemm128(const float* __restrict__ A, const float* __restrict__ W,
             float* __restrict__ C, const float* __restrict__ bias,
             int N, int lda, int ldw, int kchunk) {
    __shared__ float As[2][GBK][GBM + 4];
    __shared__ float Ws[2][GBK][GBN + 4];

    int n0 = blockIdx.x * GBN;
    int m0 = blockIdx.y * GBM;
    int kb = blockIdx.z * kchunk;
    int ke = kb + kchunk;

    int tid = threadIdx.x;
    int lr = tid >> 1;
    int lk = (tid & 1) * 8;
    int tx = tid & 15, ty = tid >> 4;

    const float* ap = A + (size_t)(m0 + lr)*lda + lk;
    bool wok = (n0 + lr) < N;
    const float* wp = W + (size_t)(wok ? (n0 + lr) : 0)*ldw + lk;

    float acc[8][8];
    #pragma unroll
    for (int i = 0; i < 8; i++)
        #pragma unroll
        for (int j = 0; j < 8; j++) acc[i][j] = 0.f;

    // prologue
    float4 ra0 = *(const float4*)(ap + kb);
    float4 ra1 = *(const float4*)(ap + kb + 4);
    float4 rw0, rw1;
    if (wok) { rw0 = *(const float4*)(wp + kb); rw1 = *(const float4*)(wp + kb + 4); }
    else     { rw0 = make_float4(0,0,0,0); rw1 = rw0; }

    As[0][lk+0][lr] = ra0.x; As[0][lk+1][lr] = ra0.y;
    As[0][lk+2][lr] = ra0.z; As[0][lk+3][lr] = ra0.w;
    As[0][lk+4][lr] = ra1.x; As[0][lk+5][lr] = ra1.y;
    As[0][lk+6][lr] = ra1.z; As[0][lk+7][lr] = ra1.w;
    Ws[0][lk+0][lr] = rw0.x; Ws[0][lk+1][lr] = rw0.y;
    Ws[0][lk+2][lr] = rw0.z; Ws[0][lk+3][lr] = rw0.w;
    Ws[0][lk+4][lr] = rw1.x; Ws[0][lk+5][lr] = rw1.y;
    Ws[0][lk+6][lr] = rw1.z; Ws[0][lk+7][lr] = rw1.w;
    __syncthreads();

    int buf = 0;
    for (int k0 = kb; k0 < ke; k0 += GBK) {
        bool has_next = (k0 + GBK) < ke;
        if (has_next) {
            ra0 = *(const float4*)(ap + k0 + GBK);
            ra1 = *(const float4*)(ap + k0 + GBK + 4);
            if (wok) { rw0 = *(const float4*)(wp + k0 + GBK); rw1 = *(const float4*)(wp + k0 + GBK + 4); }
        }
        #pragma unroll
        for (int kk = 0; kk < GBK; kk++) {
            float4 a0 = *(const float4*)&As[buf][kk][ty*4];
            float4 a1 = *(const float4*)&As[buf][kk][64 + ty*4];
            float4 b0 = *(const float4*)&Ws[buf][kk][tx*4];
            float4 b1 = *(const float4*)&Ws[buf][kk][64 + tx*4];
            float ar[8], br[8];
            ar[0]=a0.x; ar[1]=a0.y; ar[2]=a0.z; ar[3]=a0.w;
            ar[4]=a1.x; ar[5]=a1.y; ar[6]=a1.z; ar[7]=a1.w;
            br[0]=b0.x; br[1]=b0.y; br[2]=b0.z; br[3]=b0.w;
            br[4]=b1.x; br[5]=b1.y; br[6]=b1.z; br[7]=b1.w;
            #pragma unroll
            for (int i = 0; i < 8; i++)
                #pragma unroll
                for (int j = 0; j < 8; j++)
                    acc[i][j] = fmaf(ar[i], br[j], acc[i][j]);
        }
        if (has_next) {
            int nb = buf ^ 1;
            As[nb][lk+0][lr] = ra0.x; As[nb][lk+1][lr] = ra0.y;
            As[nb][lk+2][lr] = ra0.z; As[nb][lk+3][lr] = ra0.w;
            As[nb][lk+4][lr] = ra1.x; As[nb][lk+5][lr] = ra1.y;
            As[nb][lk+6][lr] = ra1.z; As[nb][lk+7][lr] = ra1.w;
            Ws[nb][lk+0][lr] = rw0.x; Ws[nb][lk+1][lr] = rw0.y;
            Ws[nb][lk+2][lr] = rw0.z; Ws[nb][lk+3][lr] = rw0.w;
            Ws[nb][lk+4][lr] = rw1.x; Ws[nb][lk+5][lr] = rw1.y;
            Ws[nb][lk+6][lr] = rw1.z; Ws[nb][lk+7][lr] = rw1.w;
            __syncthreads();
            buf = nb;
        }
    }

    // epilogue
    #pragma unroll
    for (int qa = 0; qa < 2; qa++) {
        #pragma unroll
        for (int i = 0; i < 4; i++) {
            int m = m0 + qa*64 + ty*4 + i;
            #pragma unroll
            for (int qb = 0; qb < 2; qb++) {
                int n = n0 + qb*64 + tx*4;
                if (EPI == 0) {
                    float4 v = make_float4(acc[qa*4+i][qb*4+0], acc[qa*4+i][qb*4+1],
                                           acc[qa*4+i][qb*4+2], acc[qa*4+i][qb*4+3]);
                    *(float4*)&C[(size_t)m*N + n] = v;
                } else {
                    #pragma unroll
                    for (int j = 0; j < 4; j++) {
                        int nn = n + j;
                        if (nn >= N) continue;
                        size_t idx = (size_t)m*N + nn;
                        float v = acc[qa*4+i][qb*4+j];
                        if (EPI == 1)      C[idx] += v;
                        else if (EPI == 2) {
                            float t = v + bias[nn];
                            C[idx] = (t > 20.f) ? t : log1pf(expf(t));
                        } else {
                            atomicAdd(&C[idx], v);
                        }
                    }
                }
            }
        }
    }
}

// ---------------- depthwise causal conv + bias + silu ----------------
__global__ void conv_silu_kernel(const float* __restrict__ cw,
                                 const float* __restrict__ cb) {
    int i = blockIdx.x * blockDim.x + threadIdx.x;
    if (i >= NROWS*DI) return;
    int d = i % DI;
    int row = i / DI;
    int t = row % LL, b = row / LL;
    float w0 = cw[d*DCV + 0], w1 = cw[d*DCV + 1], w2 = cw[d*DCV + 2], w3 = cw[d*DCV + 3];
    float acc = cb[d];
    const float* base = g_XZ + (size_t)(b*LL)*(2*DI) + d;
    if (t >= 3) acc += base[(size_t)(t-3)*(2*DI)] * w0;
    if (t >= 2) acc += base[(size_t)(t-2)*(2*DI)] * w1;
    if (t >= 1) acc += base[(size_t)(t-1)*(2*DI)] * w2;
    acc += base[(size_t)t*(2*DI)] * w3;
    g_U[i] = acc / (1.f + expf(-acc));
}

// ---------------- selective scan + skip + gating ----------------
__global__ void scan_kernel(const float* __restrict__ A_log_l,
                            const float* __restrict__ D_l) {
    int g = threadIdx.x >> 4;
    int s = threadIdx.x & 15;
    int ch = blockIdx.x * 16 + g;
    int b = ch / DI, d = ch % DI;

    float A = -expf(A_log_l[d*DS + s]);
    float Dd = D_l[d];
    float h = 0.f;

    const float* delta_p = g_DELTA + (size_t)(b*LL)*DI + d;
    const float* u_p     = g_U     + (size_t)(b*LL)*DI + d;
    const float* z_p     = g_XZ    + (size_t)(b*LL)*(2*DI) + DI + d;
    const float* dbc_p   = g_DBC   + (size_t)(b*LL)*DXP;
    float* y_p           = g_Y     + (size_t)(b*LL)*DI + d;

    for (int t = 0; t < LL; t++) {
        float dt = delta_p[(size_t)t*DI];
        float ut = u_p[(size_t)t*DI];
        float Bs = dbc_p[(size_t)t*DXP + DR + s];
        float Cs = dbc_p[(size_t)t*DXP + DR + DS + s];
        float dA = __expf(dt * A);
        h = dA * h + (dt * ut) * Bs;
        float yv = h * Cs;
        yv += __shfl_down_sync(0xffffffffu, yv, 8, 16);
        yv += __shfl_down_sync(0xffffffffu, yv, 4, 16);
        yv += __shfl_down_sync(0xffffffffu, yv, 2, 16);
        yv += __shfl_down_sync(0xffffffffu, yv, 1, 16);
        if (s == 0) {
            float z = z_p[(size_t)t*(2*DI)];
            float silu_z = z / (1.f + __expf(-z));
            y_p[(size_t)t*DI] = (yv + ut * Dd) * silu_z;
        }
    }
}

// ---------------- heads ----------------
__global__ void topic_kernel(const float* __restrict__ xfin,
                             const float* __restrict__ tw,
                             const float* __restrict__ tb,
                             float* __restrict__ out) {
    int w = threadIdx.x >> 5, lane = threadIdx.x & 31;
    if (w >= BB*3) return;
    int b = w / 3, c = w % 3;
    const float* p  = xfin + (size_t)(b*LL)*DM;
    const float* wt = tw + (size_t)c*DM;
    float s = 0.f;
    for (int i = lane; i < DM; i += 32) s += p[i] * wt[i];
    for (int o = 16; o; o >>= 1) s += __shfl_down_sync(0xffffffffu, s, o);
    if (lane == 0) out[b*3 + c] = s + tb[c];
}

__global__ void loss_kernel(float* __restrict__ out, const int* __restrict__ labels) {
    if (threadIdx.x != 0 || blockIdx.x != 0) return;
    float sum = 0.f, cnt = 0.f;
    for (int b = 0; b < BB; b++) {
        float t0 = out[b*3+0], t1 = out[b*3+1], t2 = out[b*3+2];
        float m = fmaxf(t0, fmaxf(t1, t2));
        float lse = m + logf(expf(t0-m) + expf(t1-m) + expf(t2-m));
        int lab = labels[b];
        float nll = lse - out[b*3 + lab];
        if (lab != 0) { sum += nll; cnt += 1.f; }
    }
    out[6] = sum / fmaxf(cnt, 1.f);
}

// ---------------- driver ----------------
extern "C" void kernel_launch(void* const* d_in, const int* in_sizes, int n_in,
                              void* d_out, int out_size) {
    const int*   tokens    = (const int*)  d_in[0];
    const int*   labels    = (const int*)  d_in[1];
    const float* emb       = (const float*)d_in[2];
    const float* in_proj_w = (const float*)d_in[3];
    const float* conv_w    = (const float*)d_in[4];
    const float* conv_b    = (const float*)d_in[5];
    const float* x_proj_w  = (const float*)d_in[6];
    const float* dt_proj_w = (const float*)d_in[7];
    const float* dt_proj_b = (const float*)d_in[8];
    const float* A_log     = (const float*)d_in[9];
    const float* Dp        = (const float*)d_in[10];
    const float* out_proj_w= (const float*)d_in[11];
    const float* norm_w    = (const float*)d_in[12];
    const float* norm_f_w  = (const float*)d_in[13];
    const float* topic_w   = (const float*)d_in[14];
    const float* topic_b   = (const float*)d_in[15];
    float* out = (float*)d_out;

    float *pH, *pXN, *pXZ, *pU, *pDBC, *pDELTA, *pY;
    cudaGetSymbolAddress((void**)&pH,     g_H);
    cudaGetSymbolAddress((void**)&pXN,    g_XN);
    cudaGetSymbolAddress((void**)&pXZ,    g_XZ);
    cudaGetSymbolAddress((void**)&pU,     g_U);
    cudaGetSymbolAddress((void**)&pDBC,   g_DBC);
    cudaGetSymbolAddress((void**)&pDELTA, g_DELTA);
    cudaGetSymbolAddress((void**)&pY,     g_Y);

    embed_kernel<<<(NROWS*DM + 255)/256, 256>>>(tokens, emb);

    for (int l = 0; l < NLAY; l++) {
        const float* ipw = in_proj_w + (size_t)l * 2*DI * DM;
        const float* cw  = conv_w    + (size_t)l * DI * DCV;
        const float* cb  = conv_b    + (size_t)l * DI;
        const float* xpw = x_proj_w  + (size_t)l * DXP * DI;
        const float* dpw = dt_proj_w + (size_t)l * DI * DR;
        const float* dpb = dt_proj_b + (size_t)l * DI;
        const float* Al  = A_log     + (size_t)l * DI * DS;
        const float* Dl  = Dp        + (size_t)l * DI;
        const float* opw = out_proj_w+ (size_t)l * DM * DI;
        const float* nw  = norm_w    + (size_t)l * DM;

        rmsnorm_kernel<<<NROWS, 256>>>(pH, nw, pXN);

        // XZ = XN @ in_proj^T  (4096 x 3072, K=768)
        {
            dim3 grid(2*DI/GBN, NROWS/GBM, 1);
            gemm128<0><<<grid, 256>>>(pXN, ipw, pXZ, nullptr, 2*DI, DM, DM, DM);
        }

        conv_silu_kernel<<<(NROWS*DI + 255)/256, 256>>>(cw, cb);

        // DBC = U @ x_proj^T  (4096 x 80, K=1536)  split-K=8 atomic
        zero_kernel<<<(NROWS*DXP + 255)/256, 256>>>(pDBC, NROWS*DXP);
        {
            dim3 grid(1, NROWS/GBM, 8);
            gemm128<3><<<grid, 256>>>(pU, xpw, pDBC, nullptr, DXP, DI, DI, DI/8);
        }

        // DELTA = softplus(DBC[:, :48] @ dt_proj^T + b)  (4096 x 1536, K=48)
        {
            dim3 grid(DI/GBN, NROWS/GBM, 1);
            gemm128<2><<<grid, 256>>>(pDBC, dpw, pDELTA, dpb, DI, DXP, DR, DR);
        }

        scan_kernel<<<BB*DI/16, 256>>>(Al, Dl);

        // H += Y @ out_proj^T  (4096 x 768, K=1536)  split-K=2 atomic into residual
        {
            dim3 grid(DM/GBN, NROWS/GBM, 2);
            gemm128<3><<<grid, 256>>>(pY, opw, pH, nullptr, DM, DI, DI, DI/2);
        }
    }

    rmsnorm_kernel<<<NROWS, 256>>>(pH, norm_f_w, out + 7);
    topic_kernel<<<1, 192>>>(out + 7, topic_w, topic_b, out);
    loss_kernel<<<1, 1>>>(out, labels);
}